// round 14
// baseline (speedup 1.0000x reference)
#include <cuda_runtime.h>
#include <cstdint>

// reconstruction_loss: mean(sqrt(d^2 + 1e-6)) over mosaic-gathered pixels
//   X, Y: [8, 16, 512, 512] fp32, channel c = (h%4)*4 + (w%4)
//
// FINAL (converged R2..R13): timed graph replays are L2-resident and run at
// ~95% of the path-independent LTS service cap (~6300 B/cyc): 64MB
// irreducible sector traffic / ~10.2us = 6.6 TB/s. The 4x sector
// amplification is geometric (2 of 8 floats per 32B sector are ever needed
// at those coordinates) and cannot be reduced by any load path. Tested and
// plateaued at 10.72us: fusion, MLP batching, float4/v8 vectorization, L2
// eviction hints (regressed), occupancy 10-81%, grids 128-1024 blocks.
// Best config: dense float4 gather (fully coalesced 512B warp streams per
// plane), 256x256, fused self-resetting last-block reduction.

#define N_ELEM (8 * 512 * 512)   // 2097152 gathered pixels
#define NBLK 256
#define NTHR 256

__device__ float g_partial[NBLK];
__device__ unsigned int g_count = 0;

__global__ void __launch_bounds__(NTHR)
msfa_loss_fused(const float* __restrict__ X, const float* __restrict__ Y,
                float* __restrict__ out) {
    int t = blockIdx.x * NTHR + threadIdx.x;   // [0, 65536): 4 pixels each
    int h  = t >> 7;                           // row
    int w4 = (t & 127) << 2;                   // col base, multiple of 4
    int r  = (h & 3) << 2;                     // plane group for this row

    // offset = (c << 18) + (h << 9) + w4 ; plane c_j = r + j
    size_t base = ((size_t)r << 18) + ((size_t)h << 9) + (size_t)w4;
    const float4* __restrict__ x0 = (const float4*)(X + base);
    const float4* __restrict__ y0 = (const float4*)(Y + base);
    const int PS = 1 << 16;      // plane stride (float4 units)
    const int BS = 1 << 20;      // batch stride (float4 units)

    float acc = 0.0f;
#pragma unroll 2
    for (int b = 0; b < 8; b++) {
        int bo = b * BS;
        // 8 dense vector loads per batch (4 planes x {X, Y})
        float4 xa = x0[bo];          float4 ya = y0[bo];
        float4 xb = x0[bo + PS];     float4 yb = y0[bo + PS];
        float4 xc = x0[bo + 2*PS];   float4 yc = y0[bo + 2*PS];
        float4 xd = x0[bo + 3*PS];   float4 yd = y0[bo + 3*PS];
        // pixel w4+j uses element j of plane r+j
        float d0 = xa.x - ya.x;
        float d1 = xb.y - yb.y;
        float d2 = xc.z - yc.z;
        float d3 = xd.w - yd.w;
        float s0 = __fmaf_rn(d0, d0, 1e-6f);
        float s1 = __fmaf_rn(d1, d1, 1e-6f);
        float s2 = __fmaf_rn(d2, d2, 1e-6f);
        float s3 = __fmaf_rn(d3, d3, 1e-6f);
        float v0, v1, v2, v3;
        asm("sqrt.approx.f32 %0, %1;" : "=f"(v0) : "f"(s0));
        asm("sqrt.approx.f32 %0, %1;" : "=f"(v1) : "f"(s1));
        asm("sqrt.approx.f32 %0, %1;" : "=f"(v2) : "f"(s2));
        asm("sqrt.approx.f32 %0, %1;" : "=f"(v3) : "f"(s3));
        acc += (v0 + v1) + (v2 + v3);
    }

    // deterministic in-block reduction: warp shfl tree, then smem across warps
#pragma unroll
    for (int o = 16; o; o >>= 1)
        acc += __shfl_xor_sync(0xFFFFFFFFu, acc, o);

    __shared__ float red[NTHR / 32];
    __shared__ bool is_last;
    if ((threadIdx.x & 31) == 0) red[threadIdx.x >> 5] = acc;
    __syncthreads();

    if (threadIdx.x == 0) {
        float s = 0.0f;
#pragma unroll
        for (int i = 0; i < NTHR / 32; i++) s += red[i];
        g_partial[blockIdx.x] = s;
        __threadfence();
        unsigned int old = atomicAdd(&g_count, 1u);
        is_last = (old == NBLK - 1);
    }
    __syncthreads();

    if (is_last) {
        // all other partials are published (threadfence + atomic ordering);
        // fixed indices, fixed order -> bit-deterministic result
        int tid = threadIdx.x;
        volatile const float* gp = g_partial;
        float a = gp[tid];
#pragma unroll
        for (int o = 16; o; o >>= 1)
            a += __shfl_xor_sync(0xFFFFFFFFu, a, o);

        if ((tid & 31) == 0) red[tid >> 5] = a;
        __syncthreads();
        if (tid == 0) {
            float s = 0.0f;
#pragma unroll
            for (int i = 0; i < NTHR / 32; i++) s += red[i];
            out[0] = s * (1.0f / (float)N_ELEM);
            g_count = 0;   // reset for next graph replay
        }
    }
}

extern "C" void kernel_launch(void* const* d_in, const int* in_sizes, int n_in,
                              void* d_out, int out_size) {
    const float* X = (const float*)d_in[0];
    const float* Y = (const float*)d_in[1];
    msfa_loss_fused<<<NBLK, NTHR>>>(X, Y, (float*)d_out);
}